// round 1
// baseline (speedup 1.0000x reference)
#include <cuda_runtime.h>
#include <math_constants.h>

#define B_DIM 8
#define S_DIM 4096
#define H_DIM 1024
#define N_SPANS 100
#define MAX_LEN 64

// H_DIM/4 float4 lanes per row
#define W (H_DIM / 4)   // 256

__device__ __forceinline__ float4 fmax4(float4 a, float4 b) {
    float4 r;
    r.x = fmaxf(a.x, b.x);
    r.y = fmaxf(a.y, b.y);
    r.z = fmaxf(a.z, b.z);
    r.w = fmaxf(a.w, b.w);
    return r;
}

__global__ __launch_bounds__(W, 8)
void maxpool_spans_kernel(const float* __restrict__ ctx,
                          const int* __restrict__ begins,
                          const int* __restrict__ lens,
                          float* __restrict__ out) {
    const int span = blockIdx.x;              // 0 .. B*N_SPANS-1
    const int b    = span / N_SPANS;

    const int begin = begins[span];
    int len = lens[span];
    len = len < 1 ? 1 : len;

    const int tid = threadIdx.x;              // 0..255, one float4 column

    // Base row pointer for this span (clip start defensively; per-row idx also clipped)
    const long long ctx_base = (long long)b * S_DIM * H_DIM;

    const float NEG = -CUDART_INF_F;
    float4 m0 = make_float4(NEG, NEG, NEG, NEG);
    float4 m1 = m0, m2 = m0, m3 = m0;

    int p = 0;
    // Unroll by 4: 4 independent outstanding 16B loads per thread (MLP >= 4)
    for (; p + 4 <= len; p += 4) {
        int r0 = min(begin + p,     S_DIM - 1);
        int r1 = min(begin + p + 1, S_DIM - 1);
        int r2 = min(begin + p + 2, S_DIM - 1);
        int r3 = min(begin + p + 3, S_DIM - 1);
        const float4* row0 = (const float4*)(ctx + ctx_base + (long long)r0 * H_DIM);
        const float4* row1 = (const float4*)(ctx + ctx_base + (long long)r1 * H_DIM);
        const float4* row2 = (const float4*)(ctx + ctx_base + (long long)r2 * H_DIM);
        const float4* row3 = (const float4*)(ctx + ctx_base + (long long)r3 * H_DIM);
        float4 v0 = __ldg(&row0[tid]);
        float4 v1 = __ldg(&row1[tid]);
        float4 v2 = __ldg(&row2[tid]);
        float4 v3 = __ldg(&row3[tid]);
        m0 = fmax4(m0, v0);
        m1 = fmax4(m1, v1);
        m2 = fmax4(m2, v2);
        m3 = fmax4(m3, v3);
    }
    for (; p < len; p++) {
        int r = min(begin + p, S_DIM - 1);
        const float4* row = (const float4*)(ctx + ctx_base + (long long)r * H_DIM);
        m0 = fmax4(m0, __ldg(&row[tid]));
    }

    m0 = fmax4(m0, m1);
    m2 = fmax4(m2, m3);
    m0 = fmax4(m0, m2);

    float4* o = (float4*)(out + (long long)span * H_DIM);
    o[tid] = m0;
}

extern "C" void kernel_launch(void* const* d_in, const int* in_sizes, int n_in,
                              void* d_out, int out_size) {
    const float* ctx    = (const float*)d_in[0];   // [B, S, H] float32
    const int*   begins = (const int*)d_in[1];     // [B, N_SPANS] int32
    const int*   lens   = (const int*)d_in[2];     // [B, N_SPANS] int32
    float* out = (float*)d_out;                    // [B, N_SPANS, H] float32

    dim3 grid(B_DIM * N_SPANS);
    dim3 block(W);
    maxpool_spans_kernel<<<grid, block>>>(ctx, begins, lens, out);
}

// round 2
// speedup vs baseline: 1.1735x; 1.1735x over previous
#include <cuda_runtime.h>
#include <math_constants.h>

#define B_DIM 8
#define S_DIM 4096
#define H_DIM 1024
#define N_SPANS 100
#define MAX_LEN 64
#define CHUNK 16
#define N_CHUNKS (MAX_LEN / CHUNK)   // 4

#define W (H_DIM / 4)   // 256 float4 lanes per row

__device__ __forceinline__ float4 fmax4(float4 a, float4 b) {
    float4 r;
    r.x = fmaxf(a.x, b.x);
    r.y = fmaxf(a.y, b.y);
    r.z = fmaxf(a.z, b.z);
    r.w = fmaxf(a.w, b.w);
    return r;
}

// Order-preserving float atomic max (result stored as a normal float):
//  - nonneg floats: int ordering == float ordering  -> atomicMax(int)
//  - negative floats: unsigned ordering is reversed -> atomicMin(uint)
// Mixed-sign races resolve correctly in both directions.
__device__ __forceinline__ void atomicMaxFloat(float* addr, float v) {
    int vi = __float_as_int(v);
    if (vi >= 0) {
        atomicMax((int*)addr, vi);
    } else {
        atomicMin((unsigned int*)addr, (unsigned int)vi);
    }
}

__global__ __launch_bounds__(W)
void init_out_kernel(float* __restrict__ out) {
    // one CTA per span; each thread writes one float4 of -inf
    const float NEG = -CUDART_INF_F;
    float4 v = make_float4(NEG, NEG, NEG, NEG);
    float4* o = (float4*)(out + (long long)blockIdx.x * H_DIM);
    o[threadIdx.x] = v;
}

__global__ __launch_bounds__(W)
void maxpool_chunks_kernel(const float* __restrict__ ctx,
                           const int* __restrict__ begins,
                           const int* __restrict__ lens,
                           float* __restrict__ out) {
    const int span  = blockIdx.x;           // 0 .. B*N_SPANS-1
    const int chunk = blockIdx.y;           // 0 .. N_CHUNKS-1
    const int b     = span / N_SPANS;

    int len = lens[span];
    len = len < 1 ? 1 : len;

    const int start = chunk * CHUNK;
    if (start >= len) return;               // empty chunk: exit immediately
    const int rows = min(CHUNK, len - start);

    const int begin = begins[span] + start; // guaranteed in [0, S-1] by construction
    const int tid = threadIdx.x;

    const float4* base = (const float4*)(ctx + (long long)b * S_DIM * H_DIM
                                             + (long long)begin * H_DIM);

    const float NEG = -CUDART_INF_F;
    float4 m0 = make_float4(NEG, NEG, NEG, NEG);
    float4 m1 = m0, m2 = m0, m3 = m0;

    int p = 0;
    // 8 independent outstanding 16B loads per thread per iteration (MLP = 8)
    for (; p + 8 <= rows; p += 8) {
        float4 v0 = __ldg(&base[(long long)(p + 0) * W + tid]);
        float4 v1 = __ldg(&base[(long long)(p + 1) * W + tid]);
        float4 v2 = __ldg(&base[(long long)(p + 2) * W + tid]);
        float4 v3 = __ldg(&base[(long long)(p + 3) * W + tid]);
        float4 v4 = __ldg(&base[(long long)(p + 4) * W + tid]);
        float4 v5 = __ldg(&base[(long long)(p + 5) * W + tid]);
        float4 v6 = __ldg(&base[(long long)(p + 6) * W + tid]);
        float4 v7 = __ldg(&base[(long long)(p + 7) * W + tid]);
        m0 = fmax4(m0, v0);
        m1 = fmax4(m1, v1);
        m2 = fmax4(m2, v2);
        m3 = fmax4(m3, v3);
        m0 = fmax4(m0, v4);
        m1 = fmax4(m1, v5);
        m2 = fmax4(m2, v6);
        m3 = fmax4(m3, v7);
    }
    if (p + 4 <= rows) {
        float4 v0 = __ldg(&base[(long long)(p + 0) * W + tid]);
        float4 v1 = __ldg(&base[(long long)(p + 1) * W + tid]);
        float4 v2 = __ldg(&base[(long long)(p + 2) * W + tid]);
        float4 v3 = __ldg(&base[(long long)(p + 3) * W + tid]);
        m0 = fmax4(m0, v0);
        m1 = fmax4(m1, v1);
        m2 = fmax4(m2, v2);
        m3 = fmax4(m3, v3);
        p += 4;
    }
    for (; p < rows; p++) {
        m0 = fmax4(m0, __ldg(&base[(long long)p * W + tid]));
    }

    m0 = fmax4(m0, m1);
    m2 = fmax4(m2, m3);
    m0 = fmax4(m0, m2);

    float* o = out + (long long)span * H_DIM + tid * 4;
    atomicMaxFloat(o + 0, m0.x);
    atomicMaxFloat(o + 1, m0.y);
    atomicMaxFloat(o + 2, m0.z);
    atomicMaxFloat(o + 3, m0.w);
}

extern "C" void kernel_launch(void* const* d_in, const int* in_sizes, int n_in,
                              void* d_out, int out_size) {
    const float* ctx    = (const float*)d_in[0];   // [B, S, H] float32
    const int*   begins = (const int*)d_in[1];     // [B, N_SPANS] int32
    const int*   lens   = (const int*)d_in[2];     // [B, N_SPANS] int32
    float* out = (float*)d_out;                    // [B, N_SPANS, H] float32

    init_out_kernel<<<B_DIM * N_SPANS, W>>>(out);

    dim3 grid(B_DIM * N_SPANS, N_CHUNKS);
    maxpool_chunks_kernel<<<grid, W>>>(ctx, begins, lens, out);
}